// round 2
// baseline (speedup 1.0000x reference)
#include <cuda_runtime.h>
#include <cuda_bf16.h>
#include <math.h>

// Problem constants
#define BATCH 512
#define NTOK 85
#define DIM 512
#define HEADS 8
#define HD 64
#define HALF 16
#define M_ROWS (BATCH * NTOK)          // 43520
#define FFN 2048
#define QKVN 1536

// Scratch (device globals; no allocation allowed)
static __device__ float g_x[M_ROWS * DIM];
static __device__ float g_h[M_ROWS * DIM];
static __device__ float g_qkv[M_ROWS * QKVN];
static __device__ float g_attno[M_ROWS * DIM];
static __device__ float g_fc1[M_ROWS * FFN];

// ---------------------------------------------------------------------------
// Warp reductions
__device__ __forceinline__ float wred_sum(float v) {
    #pragma unroll
    for (int o = 16; o; o >>= 1) v += __shfl_xor_sync(0xFFFFFFFFu, v, o);
    return v;
}
__device__ __forceinline__ float wred_max(float v) {
    #pragma unroll
    for (int o = 16; o; o >>= 1) v = fmaxf(v, __shfl_xor_sync(0xFFFFFFFFu, v, o));
    return v;
}

// ---------------------------------------------------------------------------
// LayerNorm: one warp per row of 512
__global__ void ln_kernel(const float* __restrict__ x, const float* __restrict__ w,
                          const float* __restrict__ b, float* __restrict__ y) {
    int row = blockIdx.x * 8 + (threadIdx.x >> 5);
    int lane = threadIdx.x & 31;
    if (row >= M_ROWS) return;
    const float* xr = x + (size_t)row * DIM;
    float v[16];
    float s = 0.f, s2 = 0.f;
    #pragma unroll
    for (int i = 0; i < 16; i++) {
        float t = xr[lane + i * 32];
        v[i] = t; s += t; s2 += t * t;
    }
    s = wred_sum(s); s2 = wred_sum(s2);
    float mu = s * (1.f / DIM);
    float var = s2 * (1.f / DIM) - mu * mu;
    float rstd = rsqrtf(var + 1e-5f);
    float* yr = y + (size_t)row * DIM;
    #pragma unroll
    for (int i = 0; i < 16; i++) {
        int d = lane + i * 32;
        yr[d] = (v[i] - mu) * rstd * w[d] + b[d];
    }
}

// ---------------------------------------------------------------------------
// GEMM: C[M,N] = A[M,K] @ W[K,N] + bias  (+ epilogue)
// EPI: 0 = bias only, 1 = bias+GELU(exact), 2 = bias+residual
// BM=BN=64, BK=16, 256 threads, 4x4 microtile. M,N,K multiples of 64/64/16.
template <int EPI>
__global__ void gemm_kernel(const float* __restrict__ A, const float* __restrict__ W,
                            const float* __restrict__ bias, const float* __restrict__ res,
                            float* __restrict__ C, int M, int N, int K) {
    __shared__ float As[16][68];   // [k][m], pad keeps float4 alignment (68*4=272 = 17*16)
    __shared__ float Bs[16][64];   // [k][n]
    const int bm = blockIdx.y * 64, bn = blockIdx.x * 64;
    const int tid = threadIdx.x;
    const int tm = tid >> 4, tn = tid & 15;

    const int arow = tid >> 2;          // 0..63
    const int acol4 = (tid & 3) * 4;    // 0,4,8,12
    const int brow = tid >> 4;          // 0..15
    const int bcol4 = (tid & 15) * 4;

    const float* Aptr = A + (size_t)(bm + arow) * K + acol4;
    const float* Wptr = W + (size_t)brow * N + bn + bcol4;

    float acc[4][4] = {};
    for (int k0 = 0; k0 < K; k0 += 16) {
        float4 a4 = *(const float4*)(Aptr + k0);
        As[acol4 + 0][arow] = a4.x;
        As[acol4 + 1][arow] = a4.y;
        As[acol4 + 2][arow] = a4.z;
        As[acol4 + 3][arow] = a4.w;
        *(float4*)&Bs[brow][bcol4] = *(const float4*)(Wptr + (size_t)k0 * N);
        __syncthreads();
        #pragma unroll
        for (int k = 0; k < 16; k++) {
            float4 a = *(float4*)&As[k][tm * 4];
            float4 b = *(float4*)&Bs[k][tn * 4];
            acc[0][0] += a.x * b.x; acc[0][1] += a.x * b.y; acc[0][2] += a.x * b.z; acc[0][3] += a.x * b.w;
            acc[1][0] += a.y * b.x; acc[1][1] += a.y * b.y; acc[1][2] += a.y * b.z; acc[1][3] += a.y * b.w;
            acc[2][0] += a.z * b.x; acc[2][1] += a.z * b.y; acc[2][2] += a.z * b.z; acc[2][3] += a.z * b.w;
            acc[3][0] += a.w * b.x; acc[3][1] += a.w * b.y; acc[3][2] += a.w * b.z; acc[3][3] += a.w * b.w;
        }
        __syncthreads();
    }

    float4 bb = *(const float4*)&bias[bn + tn * 4];
    #pragma unroll
    for (int i = 0; i < 4; i++) {
        int m = bm + tm * 4 + i;
        float o0 = acc[i][0] + bb.x;
        float o1 = acc[i][1] + bb.y;
        float o2 = acc[i][2] + bb.z;
        float o3 = acc[i][3] + bb.w;
        if (EPI == 1) {
            o0 = 0.5f * o0 * (1.f + erff(o0 * 0.70710678118654752f));
            o1 = 0.5f * o1 * (1.f + erff(o1 * 0.70710678118654752f));
            o2 = 0.5f * o2 * (1.f + erff(o2 * 0.70710678118654752f));
            o3 = 0.5f * o3 * (1.f + erff(o3 * 0.70710678118654752f));
        }
        if (EPI == 2) {
            float4 r4 = *(const float4*)&res[(size_t)m * N + bn + tn * 4];
            o0 += r4.x; o1 += r4.y; o2 += r4.z; o3 += r4.w;
        }
        float4 o = make_float4(o0, o1, o2, o3);
        *(float4*)&C[(size_t)m * N + bn + tn * 4] = o;
    }
}

// ---------------------------------------------------------------------------
// RoPE (2D), applied in place to q and k slices of qkv. FREQS[j]=exp(-j ln10/16)
__global__ void rope_kernel(float* __restrict__ qkv, const float* __restrict__ coords) {
    int idx = blockIdx.x * blockDim.x + threadIdx.x;
    if (idx >= M_ROWS * HEADS * HALF) return;
    int j = idx & 15;
    int h = (idx >> 4) & 7;
    int t = idx >> 7;
    int n = t % NTOK;
    if (n == 0) return;
    float cxd = coords[(n - 1) * 2 + 0];
    float cyd = coords[(n - 1) * 2 + 1];
    float freq = __expf((float)j * -0.14391156509757025f);  // -ln(10)/16
    float sx, cx, sy, cy;
    sincosf(cxd * freq * 6.283185307179586f, &sx, &cx);
    sincosf(cyd * freq * 6.283185307179586f, &sy, &cy);
    size_t base = (size_t)t * QKVN + h * HD + j;
    #pragma unroll
    for (int o = 0; o <= 512; o += 512) {  // q then k
        float x0 = qkv[base + o + 0];
        float x1 = qkv[base + o + 16];
        float x2 = qkv[base + o + 32];
        float x3 = qkv[base + o + 48];
        qkv[base + o + 0]  = x0 * cx - x1 * sx;
        qkv[base + o + 16] = x0 * sx + x1 * cx;
        qkv[base + o + 32] = x2 * cy - x3 * sy;
        qkv[base + o + 48] = x2 * sy + x3 * cy;
    }
}

// ---------------------------------------------------------------------------
// Attention: one block per (b,h). K,V staged in smem; warp per query row.
// Mask groups: [0,1), [1,5), [5,21), [21,85); allow bitmasks rows {0,3},{0,1},{0,2},{3}
__device__ __forceinline__ int tok_grp(int i) {
    return (i >= 21) ? 3 : (i >= 5) ? 2 : (i >= 1) ? 1 : 0;
}

#define KPAD 65
#define ATTN_SMEM ((NTOK * KPAD * 2 + 8 * 64 + 8 * 96) * 4)

__global__ void attn_kernel(const float* __restrict__ qkv, float* __restrict__ out) {
    extern __shared__ float sm[];
    float* Ks = sm;
    float* Vs = Ks + NTOK * KPAD;
    float* Qs = Vs + NTOK * KPAD;       // 8 warps * 64
    float* Ps = Qs + 8 * 64;            // 8 warps * 96
    const int b = blockIdx.x >> 3;
    const int h = blockIdx.x & 7;
    const int tid = threadIdx.x;
    const int warp = tid >> 5, lane = tid & 31;
    const int allow_tbl[4] = {9, 3, 5, 8};

    const size_t base = (size_t)b * NTOK * QKVN + h * HD;
    for (int i = tid; i < NTOK * HD; i += 256) {
        int n = i >> 6, d = i & 63;
        Ks[n * KPAD + d] = qkv[base + (size_t)n * QKVN + 512 + d];
        Vs[n * KPAD + d] = qkv[base + (size_t)n * QKVN + 1024 + d];
    }
    __syncthreads();

    for (int r = warp; r < NTOK; r += 8) {
        Qs[warp * 64 + lane]      = qkv[base + (size_t)r * QKVN + lane];
        Qs[warp * 64 + lane + 32] = qkv[base + (size_t)r * QKVN + lane + 32];
        __syncwarp();
        const int gi = tok_grp(r);
        const int arow = allow_tbl[gi];
        float s[3];
        float mx = -1e30f;
        #pragma unroll
        for (int t = 0; t < 3; t++) {
            int k = lane + t * 32;
            float v = -1e30f;
            if (k < NTOK) {
                float acc = 0.f;
                #pragma unroll
                for (int d = 0; d < 64; d++) acc += Qs[warp * 64 + d] * Ks[k * KPAD + d];
                bool allow = (arow >> tok_grp(k)) & 1;
                v = allow ? acc * 0.125f : -1e30f;
            }
            s[t] = v;
            mx = fmaxf(mx, v);
        }
        mx = wred_max(mx);
        float sum = 0.f;
        #pragma unroll
        for (int t = 0; t < 3; t++) {
            int k = lane + t * 32;
            if (k < NTOK) {
                float p = __expf(s[t] - mx);
                sum += p;
                Ps[warp * 96 + k] = p;
            }
        }
        sum = wred_sum(sum);
        float inv = 1.f / sum;
        __syncwarp();
        #pragma unroll
        for (int t = 0; t < 2; t++) {
            int d = lane + t * 32;
            float o = 0.f;
            for (int k = 0; k < NTOK; k++) o += Ps[warp * 96 + k] * Vs[k * KPAD + d];
            out[((size_t)b * NTOK + r) * DIM + h * HD + d] = o * inv;
        }
        __syncwarp();
    }
}

// ---------------------------------------------------------------------------
extern "C" void kernel_launch(void* const* d_in, const int* in_sizes, int n_in,
                              void* d_out, int out_size) {
    const float* x      = (const float*)d_in[0];
    const float* coords = (const float*)d_in[1];
    const float* ln1_w  = (const float*)d_in[2];
    const float* ln1_b  = (const float*)d_in[3];
    const float* qkv_w  = (const float*)d_in[4];
    const float* qkv_b  = (const float*)d_in[5];
    const float* proj_w = (const float*)d_in[6];
    const float* proj_b = (const float*)d_in[7];
    const float* ln2_w  = (const float*)d_in[8];
    const float* ln2_b  = (const float*)d_in[9];
    const float* fc1_w  = (const float*)d_in[10];
    const float* fc1_b  = (const float*)d_in[11];
    const float* fc2_w  = (const float*)d_in[12];
    const float* fc2_b  = (const float*)d_in[13];
    const float* lnf_w  = (const float*)d_in[14];
    const float* lnf_b  = (const float*)d_in[15];
    float* out = (float*)d_out;

    float *gx, *gh, *gqkv, *gattn, *gfc1;
    cudaGetSymbolAddress((void**)&gx, g_x);
    cudaGetSymbolAddress((void**)&gh, g_h);
    cudaGetSymbolAddress((void**)&gqkv, g_qkv);
    cudaGetSymbolAddress((void**)&gattn, g_attno);
    cudaGetSymbolAddress((void**)&gfc1, g_fc1);

    static int smem_set = 0;
    if (!smem_set) {
        cudaFuncSetAttribute(attn_kernel, cudaFuncAttributeMaxDynamicSharedMemorySize, ATTN_SMEM);
        smem_set = 1;
    }

    cudaMemcpyAsync(gx, x, (size_t)M_ROWS * DIM * sizeof(float), cudaMemcpyDeviceToDevice, 0);

    const int ln_grid = (M_ROWS + 7) / 8;
    const int rope_total = M_ROWS * HEADS * HALF;
    const int rope_grid = (rope_total + 255) / 256;

    for (int l = 0; l < 6; l++) {
        // LN1
        ln_kernel<<<ln_grid, 256>>>(gx, ln1_w + l * DIM, ln1_b + l * DIM, gh);
        // QKV GEMM
        gemm_kernel<0><<<dim3(QKVN / 64, M_ROWS / 64), 256>>>(
            gh, qkv_w + (size_t)l * DIM * QKVN, qkv_b + (size_t)l * QKVN, nullptr,
            gqkv, M_ROWS, QKVN, DIM);
        // RoPE on q,k
        rope_kernel<<<rope_grid, 256>>>(gqkv, coords);
        // Attention
        attn_kernel<<<BATCH * HEADS, 256, ATTN_SMEM>>>(gqkv, gattn);
        // proj GEMM + residual (in place on gx)
        gemm_kernel<2><<<dim3(DIM / 64, M_ROWS / 64), 256>>>(
            gattn, proj_w + (size_t)l * DIM * DIM, proj_b + (size_t)l * DIM, gx,
            gx, M_ROWS, DIM, DIM);
        // LN2
        ln_kernel<<<ln_grid, 256>>>(gx, ln2_w + l * DIM, ln2_b + l * DIM, gh);
        // fc1 + GELU
        gemm_kernel<1><<<dim3(FFN / 64, M_ROWS / 64), 256>>>(
            gh, fc1_w + (size_t)l * DIM * FFN, fc1_b + (size_t)l * FFN, nullptr,
            gfc1, M_ROWS, FFN, DIM);
        // fc2 + residual (in place on gx)
        gemm_kernel<2><<<dim3(DIM / 64, M_ROWS / 64), 256>>>(
            gfc1, fc2_w + (size_t)l * FFN * DIM, fc2_b + (size_t)l * DIM, gx,
            gx, M_ROWS, DIM, FFN);
    }
    // Final LN -> out
    ln_kernel<<<ln_grid, 256>>>(gx, lnf_w, lnf_b, out);
}

// round 5
// speedup vs baseline: 2.2193x; 2.2193x over previous
#include <cuda_runtime.h>
#include <cuda_bf16.h>
#include <math.h>
#include <stdint.h>

// Problem constants
#define BATCH 512
#define NTOK 85
#define DIM 512
#define HEADS 8
#define HD 64
#define M_ROWS (BATCH * NTOK)          // 43520
#define FFN 2048
#define QKVN 1536

// Weight layout offsets (transposed [N,K] bf16, per layer)
#define OFF_QKV 0
#define OFF_PROJ (QKVN * DIM)
#define OFF_FC1 (OFF_PROJ + DIM * DIM)
#define OFF_FC2 (OFF_FC1 + DIM * FFN)
#define LOFF (OFF_FC2 + FFN * DIM)     // 3145728

// Scratch (device globals; no allocation allowed)
static __device__ float g_x[M_ROWS * DIM];
static __device__ float g_qkv[M_ROWS * QKVN];
static __device__ __nv_bfloat16 g_a512hi[M_ROWS * DIM];
static __device__ __nv_bfloat16 g_a512lo[M_ROWS * DIM];
static __device__ __nv_bfloat16 g_a2048hi[M_ROWS * FFN];
static __device__ __nv_bfloat16 g_a2048lo[M_ROWS * FFN];
static __device__ __nv_bfloat16 g_whi[6 * LOFF];
static __device__ __nv_bfloat16 g_wlo[6 * LOFF];

// ---------------------------------------------------------------------------
__device__ __forceinline__ uint32_t smem_u32(const void* p) {
    uint32_t a;
    asm("{ .reg .u64 t; cvta.to.shared.u64 t, %1; cvt.u32.u64 %0, t; }" : "=r"(a) : "l"(p));
    return a;
}
__device__ __forceinline__ void cp16(uint32_t dst, const void* src) {
    asm volatile("cp.async.cg.shared.global [%0], [%1], 16;" :: "r"(dst), "l"(src));
}
__device__ __forceinline__ void ldmatrix_x4(uint32_t* r, uint32_t addr) {
    asm volatile("ldmatrix.sync.aligned.m8n8.x4.shared.b16 {%0,%1,%2,%3}, [%4];"
        : "=r"(r[0]), "=r"(r[1]), "=r"(r[2]), "=r"(r[3]) : "r"(addr));
}
__device__ __forceinline__ void mma_bf16(float* d, const uint32_t* a, const uint32_t* b) {
    asm volatile(
        "mma.sync.aligned.m16n8k16.row.col.f32.bf16.bf16.f32 "
        "{%0,%1,%2,%3}, {%4,%5,%6,%7}, {%8,%9}, {%0,%1,%2,%3};"
        : "+f"(d[0]), "+f"(d[1]), "+f"(d[2]), "+f"(d[3])
        : "r"(a[0]), "r"(a[1]), "r"(a[2]), "r"(a[3]), "r"(b[0]), "r"(b[1]));
}

// Warp reductions
__device__ __forceinline__ float wred_sum(float v) {
    #pragma unroll
    for (int o = 16; o; o >>= 1) v += __shfl_xor_sync(0xFFFFFFFFu, v, o);
    return v;
}
__device__ __forceinline__ float wred_max(float v) {
    #pragma unroll
    for (int o = 16; o; o >>= 1) v = fmaxf(v, __shfl_xor_sync(0xFFFFFFFFu, v, o));
    return v;
}
__device__ __forceinline__ void split_bf16(float v, __nv_bfloat16& h, __nv_bfloat16& l) {
    h = __float2bfloat16(v);
    l = __float2bfloat16(v - __bfloat162float(h));
}

// ---------------------------------------------------------------------------
// Weight prep: W[K,N] fp32 -> Whi/Wlo[N,K] bf16 (transpose + split)
__global__ void prep_w(const float* __restrict__ W, __nv_bfloat16* __restrict__ Whi,
                       __nv_bfloat16* __restrict__ Wlo, int K, int N) {
    __shared__ float t[32][33];
    int n0 = blockIdx.x * 32, k0 = blockIdx.y * 32;
    int tx = threadIdx.x, ty = threadIdx.y;
    #pragma unroll
    for (int i = 0; i < 32; i += 8)
        t[ty + i][tx] = W[(size_t)(k0 + ty + i) * N + n0 + tx];
    __syncthreads();
    #pragma unroll
    for (int i = 0; i < 32; i += 8) {
        float v = t[tx][ty + i];
        __nv_bfloat16 h, l;
        split_bf16(v, h, l);
        size_t o = (size_t)(n0 + ty + i) * K + k0 + tx;
        Whi[o] = h; Wlo[o] = l;
    }
}

// ---------------------------------------------------------------------------
// LayerNorm: one warp per row of 512. OUT=0: fp32 y. OUT=1: bf16 hi/lo.
template <int OUT>
__global__ void ln_kernel(const float* __restrict__ x, const float* __restrict__ w,
                          const float* __restrict__ b, float* __restrict__ y,
                          __nv_bfloat16* __restrict__ yhi, __nv_bfloat16* __restrict__ ylo) {
    int row = blockIdx.x * 8 + (threadIdx.x >> 5);
    int lane = threadIdx.x & 31;
    if (row >= M_ROWS) return;
    const float* xr = x + (size_t)row * DIM;
    float v[16];
    float s = 0.f, s2 = 0.f;
    #pragma unroll
    for (int i = 0; i < 16; i++) {
        float t = xr[lane + i * 32];
        v[i] = t; s += t; s2 += t * t;
    }
    s = wred_sum(s); s2 = wred_sum(s2);
    float mu = s * (1.f / DIM);
    float var = s2 * (1.f / DIM) - mu * mu;
    float rstd = rsqrtf(var + 1e-5f);
    #pragma unroll
    for (int i = 0; i < 16; i++) {
        int d = lane + i * 32;
        float o = (v[i] - mu) * rstd * w[d] + b[d];
        if (OUT == 0) {
            y[(size_t)row * DIM + d] = o;
        } else {
            __nv_bfloat16 h, l;
            split_bf16(o, h, l);
            yhi[(size_t)row * DIM + d] = h;
            ylo[(size_t)row * DIM + d] = l;
        }
    }
}

// ---------------------------------------------------------------------------
// mma.sync GEMM: C[M,N] = (Ahi+Alo)[M,K] @ (Bhi+Blo)[N,K]^T  (3-MMA compensated)
// BM=128, BN=128, BK=32. 256 threads = 8 warps; warp tile 64x32.
// smem per stage: 4 arrays (Ahi,Alo,Bhi,Blo) of 128 rows x pitch 40 bf16 (80B).
#define PITCHB 80
#define ARRB 10240            // 128 * 80
#define STAGEB (4 * ARRB)     // 40960
#define GSMEMB (2 * STAGEB)   // 81920

template <int EPI>
__global__ void __launch_bounds__(256, 1)
mma_gemm(const __nv_bfloat16* __restrict__ Ahi, const __nv_bfloat16* __restrict__ Alo,
         const __nv_bfloat16* __restrict__ Bhi, const __nv_bfloat16* __restrict__ Blo,
         const float* __restrict__ bias, const float* __restrict__ res,
         float* __restrict__ Cf, __nv_bfloat16* __restrict__ Chi, __nv_bfloat16* __restrict__ Clo,
         int M, int N, int K) {
    extern __shared__ char smem[];
    const uint32_t sb = smem_u32(smem);
    const int tid = threadIdx.x;
    const int wid = tid >> 5, lane = tid & 31;
    const int wm = wid & 1, wn = wid >> 1;     // warp grid 2 (M) x 4 (N)
    const int bm = blockIdx.y * 128, bn = blockIdx.x * 128;
    const int KT = K >> 5;

    const __nv_bfloat16* gp[4] = {
        Ahi + (size_t)bm * K, Alo + (size_t)bm * K,
        Bhi + (size_t)bn * K, Blo + (size_t)bn * K };

    // chunk c (0..511): row=c>>2, seg=c&3 (16B). Thread does c=tid, tid+256.
    const int r0 = tid >> 2, s0 = (tid & 3);
    const int r1 = (tid + 256) >> 2, s1 = ((tid + 256) & 3);

    auto load_stage = [&](int st, int k0) {
        const uint32_t sd = sb + st * STAGEB;
        #pragma unroll
        for (int arr = 0; arr < 4; arr++) {
            cp16(sd + arr * ARRB + r0 * PITCHB + s0 * 16, gp[arr] + (size_t)r0 * K + k0 + s0 * 8);
            cp16(sd + arr * ARRB + r1 * PITCHB + s1 * 16, gp[arr] + (size_t)r1 * K + k0 + s1 * 8);
        }
        asm volatile("cp.async.commit_group;" ::: "memory");
    };

    float acc[4][4][4];
    #pragma unroll
    for (int i = 0; i < 4; i++)
        #pragma unroll
        for (int j = 0; j < 4; j++)
            #pragma unroll
            for (int f = 0; f < 4; f++) acc[i][j][f] = 0.f;

    load_stage(0, 0);

    // ldmatrix lane addressing (byte offsets within an array)
    const int arow = (lane & 15);
    const int acol = (lane >> 4) << 3;
    const int brow = (lane & 7) + ((lane >> 4) << 3);
    const int bcol = ((lane >> 3) & 1) << 3;

    for (int kt = 0; kt < KT; kt++) {
        const int st = kt & 1;
        if (kt + 1 < KT) {
            load_stage(st ^ 1, (kt + 1) << 5);
            asm volatile("cp.async.wait_group 1;" ::: "memory");
        } else {
            asm volatile("cp.async.wait_group 0;" ::: "memory");
        }
        __syncthreads();
        const uint32_t sd = sb + st * STAGEB;
        #pragma unroll
        for (int kk = 0; kk < 2; kk++) {
            uint32_t ah[4][4], al[4][4], bh[4][2], bl[4][2];
            #pragma unroll
            for (int mt = 0; mt < 4; mt++) {
                uint32_t off = (uint32_t)(wm * 64 + mt * 16 + arow) * PITCHB + (acol + kk * 16) * 2;
                ldmatrix_x4(ah[mt], sd + 0 * ARRB + off);
                ldmatrix_x4(al[mt], sd + 1 * ARRB + off);
            }
            #pragma unroll
            for (int p = 0; p < 2; p++) {
                uint32_t off = (uint32_t)(wn * 32 + p * 16 + brow) * PITCHB + (bcol + kk * 16) * 2;
                uint32_t t[4];
                ldmatrix_x4(t, sd + 2 * ARRB + off);
                bh[2 * p][0] = t[0]; bh[2 * p][1] = t[1];
                bh[2 * p + 1][0] = t[2]; bh[2 * p + 1][1] = t[3];
                ldmatrix_x4(t, sd + 3 * ARRB + off);
                bl[2 * p][0] = t[0]; bl[2 * p][1] = t[1];
                bl[2 * p + 1][0] = t[2]; bl[2 * p + 1][1] = t[3];
            }
            #pragma unroll
            for (int mt = 0; mt < 4; mt++)
                #pragma unroll
                for (int nt = 0; nt < 4; nt++) {
                    mma_bf16(acc[mt][nt], ah[mt], bh[nt]);
                    mma_bf16(acc[mt][nt], ah[mt], bl[nt]);
                    mma_bf16(acc[mt][nt], al[mt], bh[nt]);
                }
        }
        __syncthreads();
    }

    // Epilogue. Fragment (mt,nt): c0,c1 = C[r][cc,cc+1]; c2,c3 = C[r+8][cc,cc+1]
    const int er = lane >> 2, ec = (lane & 3) * 2;
    #pragma unroll
    for (int mt = 0; mt < 4; mt++) {
        #pragma unroll
        for (int nt = 0; nt < 4; nt++) {
            const int n = bn + wn * 32 + nt * 8 + ec;
            const float2 bv = *(const float2*)&bias[n];
            #pragma unroll
            for (int half = 0; half < 2; half++) {
                const int m = bm + wm * 64 + mt * 16 + er + half * 8;
                float o0 = acc[mt][nt][half * 2 + 0] + bv.x;
                float o1 = acc[mt][nt][half * 2 + 1] + bv.y;
                if (EPI == 1) {
                    o0 = 0.5f * o0 * (1.f + erff(o0 * 0.70710678118654752f));
                    o1 = 0.5f * o1 * (1.f + erff(o1 * 0.70710678118654752f));
                    __nv_bfloat16 h0, l0, h1, l1;
                    split_bf16(o0, h0, l0);
                    split_bf16(o1, h1, l1);
                    __nv_bfloat162 hp, lp;
                    hp.x = h0; hp.y = h1; lp.x = l0; lp.y = l1;
                    *(__nv_bfloat162*)&Chi[(size_t)m * N + n] = hp;
                    *(__nv_bfloat162*)&Clo[(size_t)m * N + n] = lp;
                } else {
                    if (EPI == 2) {
                        float2 rv = *(const float2*)&res[(size_t)m * N + n];
                        o0 += rv.x; o1 += rv.y;
                    }
                    float2 o = make_float2(o0, o1);
                    *(float2*)&Cf[(size_t)m * N + n] = o;
                }
            }
        }
    }
}

// ---------------------------------------------------------------------------
// RoPE (2D), in place on q,k slices of qkv
__global__ void rope_kernel(float* __restrict__ qkv, const float* __restrict__ coords) {
    int idx = blockIdx.x * blockDim.x + threadIdx.x;
    if (idx >= M_ROWS * HEADS * 16) return;
    int j = idx & 15;
    int h = (idx >> 4) & 7;
    int t = idx >> 7;
    int n = t % NTOK;
    if (n == 0) return;
    float cxd = coords[(n - 1) * 2 + 0];
    float cyd = coords[(n - 1) * 2 + 1];
    float freq = __expf((float)j * -0.14391156509757025f);
    float sx, cx, sy, cy;
    sincosf(cxd * freq * 6.283185307179586f, &sx, &cx);
    sincosf(cyd * freq * 6.283185307179586f, &sy, &cy);
    size_t base = (size_t)t * QKVN + h * HD + j;
    #pragma unroll
    for (int o = 0; o <= 512; o += 512) {
        float x0 = qkv[base + o + 0];
        float x1 = qkv[base + o + 16];
        float x2 = qkv[base + o + 32];
        float x3 = qkv[base + o + 48];
        qkv[base + o + 0]  = x0 * cx - x1 * sx;
        qkv[base + o + 16] = x0 * sx + x1 * cx;
        qkv[base + o + 32] = x2 * cy - x3 * sy;
        qkv[base + o + 48] = x2 * sy + x3 * cy;
    }
}

// ---------------------------------------------------------------------------
// Attention: one block per (b,h); output bf16 hi/lo for proj GEMM
__device__ __forceinline__ int tok_grp(int i) {
    return (i >= 21) ? 3 : (i >= 5) ? 2 : (i >= 1) ? 1 : 0;
}
#define KPAD 65
#define ATTN_SMEM ((NTOK * KPAD * 2 + 8 * 64 + 8 * 96) * 4)

__global__ void attn_kernel(const float* __restrict__ qkv,
                            __nv_bfloat16* __restrict__ ohi, __nv_bfloat16* __restrict__ olo) {
    extern __shared__ float sm[];
    float* Ks = sm;
    float* Vs = Ks + NTOK * KPAD;
    float* Qs = Vs + NTOK * KPAD;
    float* Ps = Qs + 8 * 64;
    const int b = blockIdx.x >> 3;
    const int h = blockIdx.x & 7;
    const int tid = threadIdx.x;
    const int warp = tid >> 5, lane = tid & 31;
    const int allow_tbl[4] = {9, 3, 5, 8};

    const size_t base = (size_t)b * NTOK * QKVN + h * HD;
    for (int i = tid; i < NTOK * HD; i += 256) {
        int n = i >> 6, d = i & 63;
        Ks[n * KPAD + d] = qkv[base + (size_t)n * QKVN + 512 + d];
        Vs[n * KPAD + d] = qkv[base + (size_t)n * QKVN + 1024 + d];
    }
    __syncthreads();

    for (int r = warp; r < NTOK; r += 8) {
        Qs[warp * 64 + lane]      = qkv[base + (size_t)r * QKVN + lane];
        Qs[warp * 64 + lane + 32] = qkv[base + (size_t)r * QKVN + lane + 32];
        __syncwarp();
        const int arow = allow_tbl[tok_grp(r)];
        float s[3];
        float mx = -1e30f;
        #pragma unroll
        for (int t = 0; t < 3; t++) {
            int k = lane + t * 32;
            float v = -1e30f;
            if (k < NTOK) {
                float acc = 0.f;
                #pragma unroll
                for (int d = 0; d < 64; d++) acc += Qs[warp * 64 + d] * Ks[k * KPAD + d];
                bool allow = (arow >> tok_grp(k)) & 1;
                v = allow ? acc * 0.125f : -1e30f;
            }
            s[t] = v;
            mx = fmaxf(mx, v);
        }
        mx = wred_max(mx);
        float sum = 0.f;
        #pragma unroll
        for (int t = 0; t < 3; t++) {
            int k = lane + t * 32;
            if (k < NTOK) {
                float p = __expf(s[t] - mx);
                sum += p;
                Ps[warp * 96 + k] = p;
            }
        }
        sum = wred_sum(sum);
        float inv = 1.f / sum;
        __syncwarp();
        #pragma unroll
        for (int t = 0; t < 2; t++) {
            int d = lane + t * 32;
            float o = 0.f;
            for (int k = 0; k < NTOK; k++) o += Ps[warp * 96 + k] * Vs[k * KPAD + d];
            o *= inv;
            __nv_bfloat16 hh, ll;
            split_bf16(o, hh, ll);
            size_t oidx = ((size_t)b * NTOK + r) * DIM + h * HD + d;
            ohi[oidx] = hh;
            olo[oidx] = ll;
        }
        __syncwarp();
    }
}

// ---------------------------------------------------------------------------
extern "C" void kernel_launch(void* const* d_in, const int* in_sizes, int n_in,
                              void* d_out, int out_size) {
    const float* x      = (const float*)d_in[0];
    const float* coords = (const float*)d_in[1];
    const float* ln1_w  = (const float*)d_in[2];
    const float* ln1_b  = (const float*)d_in[3];
    const float* qkv_w  = (const float*)d_in[4];
    const float* qkv_b  = (const float*)d_in[5];
    const float* proj_w = (const float*)d_in[6];
    const float* proj_b = (const float*)d_in[7];
    const float* ln2_w  = (const float*)d_in[8];
    const float* ln2_b  = (const float*)d_in[9];
    const float* fc1_w  = (const float*)d_in[10];
    const float* fc1_b  = (const float*)d_in[11];
    const float* fc2_w  = (const float*)d_in[12];
    const float* fc2_b  = (const float*)d_in[13];
    const float* lnf_w  = (const float*)d_in[14];
    const float* lnf_b  = (const float*)d_in[15];
    float* out = (float*)d_out;

    float *gx, *gqkv;
    __nv_bfloat16 *a5h, *a5l, *a2h, *a2l, *whi, *wlo;
    cudaGetSymbolAddress((void**)&gx, g_x);
    cudaGetSymbolAddress((void**)&gqkv, g_qkv);
    cudaGetSymbolAddress((void**)&a5h, g_a512hi);
    cudaGetSymbolAddress((void**)&a5l, g_a512lo);
    cudaGetSymbolAddress((void**)&a2h, g_a2048hi);
    cudaGetSymbolAddress((void**)&a2l, g_a2048lo);
    cudaGetSymbolAddress((void**)&whi, g_whi);
    cudaGetSymbolAddress((void**)&wlo, g_wlo);

    static int attr_set = 0;
    if (!attr_set) {
        cudaFuncSetAttribute(attn_kernel, cudaFuncAttributeMaxDynamicSharedMemorySize, ATTN_SMEM);
        cudaFuncSetAttribute(mma_gemm<0>, cudaFuncAttributeMaxDynamicSharedMemorySize, GSMEMB);
        cudaFuncSetAttribute(mma_gemm<1>, cudaFuncAttributeMaxDynamicSharedMemorySize, GSMEMB);
        cudaFuncSetAttribute(mma_gemm<2>, cudaFuncAttributeMaxDynamicSharedMemorySize, GSMEMB);
        attr_set = 1;
    }

    // Weight prep: transpose + bf16 hi/lo split
    for (int l = 0; l < 6; l++) {
        prep_w<<<dim3(QKVN / 32, DIM / 32), dim3(32, 8)>>>(
            qkv_w + (size_t)l * DIM * QKVN, whi + (size_t)l * LOFF + OFF_QKV,
            wlo + (size_t)l * LOFF + OFF_QKV, DIM, QKVN);
        prep_w<<<dim3(DIM / 32, DIM / 32), dim3(32, 8)>>>(
            proj_w + (size_t)l * DIM * DIM, whi + (size_t)l * LOFF + OFF_PROJ,
            wlo + (size_t)l * LOFF + OFF_PROJ, DIM, DIM);
        prep_w<<<dim3(FFN / 32, DIM / 32), dim3(32, 8)>>>(
            fc1_w + (size_t)l * DIM * FFN, whi + (size_t)l * LOFF + OFF_FC1,
            wlo + (size_t)l * LOFF + OFF_FC1, DIM, FFN);
        prep_w<<<dim3(DIM / 32, FFN / 32), dim3(32, 8)>>>(
            fc2_w + (size_t)l * FFN * DIM, whi + (size_t)l * LOFF + OFF_FC2,
            wlo + (size_t)l * LOFF + OFF_FC2, FFN, DIM);
    }

    cudaMemcpyAsync(gx, x, (size_t)M_ROWS * DIM * sizeof(float), cudaMemcpyDeviceToDevice, 0);

    const int ln_grid = (M_ROWS + 7) / 8;
    const int rope_grid = (M_ROWS * HEADS * 16 + 255) / 256;

    for (int l = 0; l < 6; l++) {
        const __nv_bfloat16* qkvT_h = whi + (size_t)l * LOFF + OFF_QKV;
        const __nv_bfloat16* qkvT_l = wlo + (size_t)l * LOFF + OFF_QKV;
        const __nv_bfloat16* projT_h = whi + (size_t)l * LOFF + OFF_PROJ;
        const __nv_bfloat16* projT_l = wlo + (size_t)l * LOFF + OFF_PROJ;
        const __nv_bfloat16* fc1T_h = whi + (size_t)l * LOFF + OFF_FC1;
        const __nv_bfloat16* fc1T_l = wlo + (size_t)l * LOFF + OFF_FC1;
        const __nv_bfloat16* fc2T_h = whi + (size_t)l * LOFF + OFF_FC2;
        const __nv_bfloat16* fc2T_l = wlo + (size_t)l * LOFF + OFF_FC2;

        // LN1 -> bf16 hi/lo
        ln_kernel<1><<<ln_grid, 256>>>(gx, ln1_w + l * DIM, ln1_b + l * DIM, nullptr, a5h, a5l);
        // QKV GEMM -> fp32 qkv
        mma_gemm<0><<<dim3(QKVN / 128, M_ROWS / 128), 256, GSMEMB>>>(
            a5h, a5l, qkvT_h, qkvT_l, qkv_b + (size_t)l * QKVN, nullptr,
            gqkv, nullptr, nullptr, M_ROWS, QKVN, DIM);
        // RoPE
        rope_kernel<<<rope_grid, 256>>>(gqkv, coords);
        // Attention -> bf16 hi/lo
        attn_kernel<<<BATCH * HEADS, 256, ATTN_SMEM>>>(gqkv, a5h, a5l);
        // proj GEMM + residual -> g_x
        mma_gemm<2><<<dim3(DIM / 128, M_ROWS / 128), 256, GSMEMB>>>(
            a5h, a5l, projT_h, projT_l, proj_b + (size_t)l * DIM, gx,
            gx, nullptr, nullptr, M_ROWS, DIM, DIM);
        // LN2 -> bf16 hi/lo
        ln_kernel<1><<<ln_grid, 256>>>(gx, ln2_w + l * DIM, ln2_b + l * DIM, nullptr, a5h, a5l);
        // fc1 + GELU -> bf16 hi/lo
        mma_gemm<1><<<dim3(FFN / 128, M_ROWS / 128), 256, GSMEMB>>>(
            a5h, a5l, fc1T_h, fc1T_l, fc1_b + (size_t)l * FFN, nullptr,
            nullptr, a2h, a2l, M_ROWS, FFN, DIM);
        // fc2 + residual -> g_x
        mma_gemm<2><<<dim3(DIM / 128, M_ROWS / 128), 256, GSMEMB>>>(
            a2h, a2l, fc2T_h, fc2T_l, fc2_b + (size_t)l * DIM, gx,
            gx, nullptr, nullptr, M_ROWS, DIM, FFN);
    }
    // Final LN -> out (fp32)
    ln_kernel<0><<<ln_grid, 256>>>(gx, lnf_w, lnf_b, out, nullptr, nullptr);
}

// round 6
// speedup vs baseline: 2.5975x; 1.1704x over previous
#include <cuda_runtime.h>
#include <cuda_bf16.h>
#include <math.h>
#include <stdint.h>

// Problem constants
#define BATCH 512
#define NTOK 85
#define DIM 512
#define HEADS 8
#define HD 64
#define M_ROWS (BATCH * NTOK)          // 43520
#define FFN 2048
#define QKVN 1536

// Weight layout offsets (transposed [N,K] bf16, per layer)
#define OFF_QKV 0
#define OFF_PROJ (QKVN * DIM)
#define OFF_FC1 (OFF_PROJ + DIM * DIM)
#define OFF_FC2 (OFF_FC1 + DIM * FFN)
#define LOFF (OFF_FC2 + FFN * DIM)     // 3145728

// Scratch (device globals; no allocation allowed)
static __device__ float g_x[M_ROWS * DIM];
static __device__ float g_qkv[M_ROWS * QKVN];
static __device__ __nv_bfloat16 g_a512hi[M_ROWS * DIM];
static __device__ __nv_bfloat16 g_a512lo[M_ROWS * DIM];
static __device__ __nv_bfloat16 g_a2048hi[M_ROWS * FFN];
static __device__ __nv_bfloat16 g_a2048lo[M_ROWS * FFN];
static __device__ __nv_bfloat16 g_whi[6 * LOFF];
static __device__ __nv_bfloat16 g_wlo[6 * LOFF];

// ---------------------------------------------------------------------------
__device__ __forceinline__ uint32_t smem_u32(const void* p) {
    uint32_t a;
    asm("{ .reg .u64 t; cvta.to.shared.u64 t, %1; cvt.u32.u64 %0, t; }" : "=r"(a) : "l"(p));
    return a;
}
__device__ __forceinline__ void cp16(uint32_t dst, const void* src) {
    asm volatile("cp.async.cg.shared.global [%0], [%1], 16;" :: "r"(dst), "l"(src));
}
__device__ __forceinline__ void ldmatrix_x4(uint32_t* r, uint32_t addr) {
    asm volatile("ldmatrix.sync.aligned.m8n8.x4.shared.b16 {%0,%1,%2,%3}, [%4];"
        : "=r"(r[0]), "=r"(r[1]), "=r"(r[2]), "=r"(r[3]) : "r"(addr));
}
__device__ __forceinline__ void mma_bf16(float* d, const uint32_t* a, const uint32_t* b) {
    asm volatile(
        "mma.sync.aligned.m16n8k16.row.col.f32.bf16.bf16.f32 "
        "{%0,%1,%2,%3}, {%4,%5,%6,%7}, {%8,%9}, {%0,%1,%2,%3};"
        : "+f"(d[0]), "+f"(d[1]), "+f"(d[2]), "+f"(d[3])
        : "r"(a[0]), "r"(a[1]), "r"(a[2]), "r"(a[3]), "r"(b[0]), "r"(b[1]));
}

// Warp reductions
__device__ __forceinline__ float wred_sum(float v) {
    #pragma unroll
    for (int o = 16; o; o >>= 1) v += __shfl_xor_sync(0xFFFFFFFFu, v, o);
    return v;
}
__device__ __forceinline__ float wred_max(float v) {
    #pragma unroll
    for (int o = 16; o; o >>= 1) v = fmaxf(v, __shfl_xor_sync(0xFFFFFFFFu, v, o));
    return v;
}
__device__ __forceinline__ void split_bf16(float v, __nv_bfloat16& h, __nv_bfloat16& l) {
    h = __float2bfloat16(v);
    l = __float2bfloat16(v - __bfloat162float(h));
}

// ---------------------------------------------------------------------------
// Weight prep: W[K,N] fp32 -> Whi/Wlo[N,K] bf16 (transpose + split)
__global__ void prep_w(const float* __restrict__ W, __nv_bfloat16* __restrict__ Whi,
                       __nv_bfloat16* __restrict__ Wlo, int K, int N) {
    __shared__ float t[32][33];
    int n0 = blockIdx.x * 32, k0 = blockIdx.y * 32;
    int tx = threadIdx.x, ty = threadIdx.y;
    #pragma unroll
    for (int i = 0; i < 32; i += 8)
        t[ty + i][tx] = W[(size_t)(k0 + ty + i) * N + n0 + tx];
    __syncthreads();
    #pragma unroll
    for (int i = 0; i < 32; i += 8) {
        float v = t[tx][ty + i];
        __nv_bfloat16 h, l;
        split_bf16(v, h, l);
        size_t o = (size_t)(n0 + ty + i) * K + k0 + tx;
        Whi[o] = h; Wlo[o] = l;
    }
}

// ---------------------------------------------------------------------------
// LayerNorm: one warp per row of 512. OUT=0: fp32 y. OUT=1: bf16 hi/lo.
template <int OUT>
__global__ void ln_kernel(const float* __restrict__ x, const float* __restrict__ w,
                          const float* __restrict__ b, float* __restrict__ y,
                          __nv_bfloat16* __restrict__ yhi, __nv_bfloat16* __restrict__ ylo) {
    int row = blockIdx.x * 8 + (threadIdx.x >> 5);
    int lane = threadIdx.x & 31;
    if (row >= M_ROWS) return;
    const float* xr = x + (size_t)row * DIM;
    float v[16];
    float s = 0.f, s2 = 0.f;
    #pragma unroll
    for (int i = 0; i < 16; i++) {
        float t = xr[lane + i * 32];
        v[i] = t; s += t; s2 += t * t;
    }
    s = wred_sum(s); s2 = wred_sum(s2);
    float mu = s * (1.f / DIM);
    float var = s2 * (1.f / DIM) - mu * mu;
    float rstd = rsqrtf(var + 1e-5f);
    #pragma unroll
    for (int i = 0; i < 16; i++) {
        int d = lane + i * 32;
        float o = (v[i] - mu) * rstd * w[d] + b[d];
        if (OUT == 0) {
            y[(size_t)row * DIM + d] = o;
        } else {
            __nv_bfloat16 h, l;
            split_bf16(o, h, l);
            yhi[(size_t)row * DIM + d] = h;
            ylo[(size_t)row * DIM + d] = l;
        }
    }
}

// ---------------------------------------------------------------------------
// mma.sync GEMM: C[M,N] = (Ahi+Alo)[M,K] @ (Bhi+Blo)[N,K]^T  (3-MMA compensated)
// BM=128, BN=128, BK=32. 256 threads = 8 warps; warp tile 64x32.
// Register-lean inner loop (B frags hoisted, A streamed) -> 2 CTAs/SM.
#define PITCHB 80
#define ARRB 10240            // 128 * 80
#define STAGEB (4 * ARRB)     // 40960
#define GSMEMB (2 * STAGEB)   // 81920

template <int EPI>
__global__ void __launch_bounds__(256, 2)
mma_gemm(const __nv_bfloat16* __restrict__ Ahi, const __nv_bfloat16* __restrict__ Alo,
         const __nv_bfloat16* __restrict__ Bhi, const __nv_bfloat16* __restrict__ Blo,
         const float* __restrict__ bias, const float* __restrict__ res,
         float* __restrict__ Cf, __nv_bfloat16* __restrict__ Chi, __nv_bfloat16* __restrict__ Clo,
         int M, int N, int K) {
    extern __shared__ char smem[];
    const uint32_t sb = smem_u32(smem);
    const int tid = threadIdx.x;
    const int wid = tid >> 5, lane = tid & 31;
    const int wm = wid & 1, wn = wid >> 1;     // warp grid 2 (M) x 4 (N)
    const int bm = blockIdx.y * 128, bn = blockIdx.x * 128;
    const int KT = K >> 5;

    const __nv_bfloat16* gp[4] = {
        Ahi + (size_t)bm * K, Alo + (size_t)bm * K,
        Bhi + (size_t)bn * K, Blo + (size_t)bn * K };

    const int r0 = tid >> 2, s0 = (tid & 3);
    const int r1 = (tid + 256) >> 2, s1 = ((tid + 256) & 3);

    auto load_stage = [&](int st, int k0) {
        const uint32_t sd = sb + st * STAGEB;
        #pragma unroll
        for (int arr = 0; arr < 4; arr++) {
            cp16(sd + arr * ARRB + r0 * PITCHB + s0 * 16, gp[arr] + (size_t)r0 * K + k0 + s0 * 8);
            cp16(sd + arr * ARRB + r1 * PITCHB + s1 * 16, gp[arr] + (size_t)r1 * K + k0 + s1 * 8);
        }
        asm volatile("cp.async.commit_group;" ::: "memory");
    };

    float acc[4][4][4];
    #pragma unroll
    for (int i = 0; i < 4; i++)
        #pragma unroll
        for (int j = 0; j < 4; j++)
            #pragma unroll
            for (int f = 0; f < 4; f++) acc[i][j][f] = 0.f;

    load_stage(0, 0);

    // ldmatrix lane addressing (byte offsets within an array)
    const int arow = (lane & 15);
    const int acol = (lane >> 4) << 3;
    const int brow = (lane & 7) + ((lane >> 4) << 3);
    const int bcol = ((lane >> 3) & 1) << 3;

    for (int kt = 0; kt < KT; kt++) {
        const int st = kt & 1;
        if (kt + 1 < KT) {
            load_stage(st ^ 1, (kt + 1) << 5);
            asm volatile("cp.async.wait_group 1;" ::: "memory");
        } else {
            asm volatile("cp.async.wait_group 0;" ::: "memory");
        }
        __syncthreads();
        const uint32_t sd = sb + st * STAGEB;
        #pragma unroll
        for (int kk = 0; kk < 2; kk++) {
            // B fragments hoisted: 16 regs live across the mt loop
            uint32_t bh[4][2], bl[4][2];
            #pragma unroll
            for (int p = 0; p < 2; p++) {
                uint32_t off = (uint32_t)(wn * 32 + p * 16 + brow) * PITCHB + (bcol + kk * 16) * 2;
                uint32_t t[4];
                ldmatrix_x4(t, sd + 2 * ARRB + off);
                bh[2 * p][0] = t[0]; bh[2 * p][1] = t[1];
                bh[2 * p + 1][0] = t[2]; bh[2 * p + 1][1] = t[3];
                ldmatrix_x4(t, sd + 3 * ARRB + off);
                bl[2 * p][0] = t[0]; bl[2 * p][1] = t[1];
                bl[2 * p + 1][0] = t[2]; bl[2 * p + 1][1] = t[3];
            }
            // A streamed: only 8 A-regs live at a time
            #pragma unroll
            for (int mt = 0; mt < 4; mt++) {
                uint32_t ah[4], al[4];
                uint32_t off = (uint32_t)(wm * 64 + mt * 16 + arow) * PITCHB + (acol + kk * 16) * 2;
                ldmatrix_x4(ah, sd + 0 * ARRB + off);
                ldmatrix_x4(al, sd + 1 * ARRB + off);
                #pragma unroll
                for (int nt = 0; nt < 4; nt++) {
                    mma_bf16(acc[mt][nt], ah, bh[nt]);
                    mma_bf16(acc[mt][nt], ah, bl[nt]);
                    mma_bf16(acc[mt][nt], al, bh[nt]);
                }
            }
        }
        __syncthreads();
    }

    // Epilogue. Fragment (mt,nt): c0,c1 = C[r][cc,cc+1]; c2,c3 = C[r+8][cc,cc+1]
    const int er = lane >> 2, ec = (lane & 3) * 2;
    #pragma unroll
    for (int mt = 0; mt < 4; mt++) {
        #pragma unroll
        for (int nt = 0; nt < 4; nt++) {
            const int n = bn + wn * 32 + nt * 8 + ec;
            const float2 bv = *(const float2*)&bias[n];
            #pragma unroll
            for (int half = 0; half < 2; half++) {
                const int m = bm + wm * 64 + mt * 16 + er + half * 8;
                float o0 = acc[mt][nt][half * 2 + 0] + bv.x;
                float o1 = acc[mt][nt][half * 2 + 1] + bv.y;
                if (EPI == 1) {
                    o0 = 0.5f * o0 * (1.f + erff(o0 * 0.70710678118654752f));
                    o1 = 0.5f * o1 * (1.f + erff(o1 * 0.70710678118654752f));
                    __nv_bfloat16 h0, l0, h1, l1;
                    split_bf16(o0, h0, l0);
                    split_bf16(o1, h1, l1);
                    __nv_bfloat162 hp, lp;
                    hp.x = h0; hp.y = h1; lp.x = l0; lp.y = l1;
                    *(__nv_bfloat162*)&Chi[(size_t)m * N + n] = hp;
                    *(__nv_bfloat162*)&Clo[(size_t)m * N + n] = lp;
                } else {
                    if (EPI == 2) {
                        float2 rv = *(const float2*)&res[(size_t)m * N + n];
                        o0 += rv.x; o1 += rv.y;
                    }
                    float2 o = make_float2(o0, o1);
                    *(float2*)&Cf[(size_t)m * N + n] = o;
                }
            }
        }
    }
}

// ---------------------------------------------------------------------------
// RoPE (2D), in place on q,k slices of qkv
__global__ void rope_kernel(float* __restrict__ qkv, const float* __restrict__ coords) {
    int idx = blockIdx.x * blockDim.x + threadIdx.x;
    if (idx >= M_ROWS * HEADS * 16) return;
    int j = idx & 15;
    int h = (idx >> 4) & 7;
    int t = idx >> 7;
    int n = t % NTOK;
    if (n == 0) return;
    float cxd = coords[(n - 1) * 2 + 0];
    float cyd = coords[(n - 1) * 2 + 1];
    float freq = __expf((float)j * -0.14391156509757025f);
    float sx, cx, sy, cy;
    sincosf(cxd * freq * 6.283185307179586f, &sx, &cx);
    sincosf(cyd * freq * 6.283185307179586f, &sy, &cy);
    size_t base = (size_t)t * QKVN + h * HD + j;
    #pragma unroll
    for (int o = 0; o <= 512; o += 512) {
        float x0 = qkv[base + o + 0];
        float x1 = qkv[base + o + 16];
        float x2 = qkv[base + o + 32];
        float x3 = qkv[base + o + 48];
        qkv[base + o + 0]  = x0 * cx - x1 * sx;
        qkv[base + o + 16] = x0 * sx + x1 * cx;
        qkv[base + o + 32] = x2 * cy - x3 * sy;
        qkv[base + o + 48] = x2 * sy + x3 * cy;
    }
}

// ---------------------------------------------------------------------------
// Attention: one block per (b,h); output bf16 hi/lo for proj GEMM
__device__ __forceinline__ int tok_grp(int i) {
    return (i >= 21) ? 3 : (i >= 5) ? 2 : (i >= 1) ? 1 : 0;
}
#define KPAD 65
#define ATTN_SMEM ((NTOK * KPAD * 2 + 8 * 64 + 8 * 96) * 4)

__global__ void attn_kernel(const float* __restrict__ qkv,
                            __nv_bfloat16* __restrict__ ohi, __nv_bfloat16* __restrict__ olo) {
    extern __shared__ float sm[];
    float* Ks = sm;
    float* Vs = Ks + NTOK * KPAD;
    float* Qs = Vs + NTOK * KPAD;
    float* Ps = Qs + 8 * 64;
    const int b = blockIdx.x >> 3;
    const int h = blockIdx.x & 7;
    const int tid = threadIdx.x;
    const int warp = tid >> 5, lane = tid & 31;
    const int allow_tbl[4] = {9, 3, 5, 8};

    const size_t base = (size_t)b * NTOK * QKVN + h * HD;
    for (int i = tid; i < NTOK * HD; i += 256) {
        int n = i >> 6, d = i & 63;
        Ks[n * KPAD + d] = qkv[base + (size_t)n * QKVN + 512 + d];
        Vs[n * KPAD + d] = qkv[base + (size_t)n * QKVN + 1024 + d];
    }
    __syncthreads();

    for (int r = warp; r < NTOK; r += 8) {
        Qs[warp * 64 + lane]      = qkv[base + (size_t)r * QKVN + lane];
        Qs[warp * 64 + lane + 32] = qkv[base + (size_t)r * QKVN + lane + 32];
        __syncwarp();
        const int arow = allow_tbl[tok_grp(r)];
        float s[3];
        float mx = -1e30f;
        #pragma unroll
        for (int t = 0; t < 3; t++) {
            int k = lane + t * 32;
            float v = -1e30f;
            if (k < NTOK) {
                float acc = 0.f;
                #pragma unroll
                for (int d = 0; d < 64; d++) acc += Qs[warp * 64 + d] * Ks[k * KPAD + d];
                bool allow = (arow >> tok_grp(k)) & 1;
                v = allow ? acc * 0.125f : -1e30f;
            }
            s[t] = v;
            mx = fmaxf(mx, v);
        }
        mx = wred_max(mx);
        float sum = 0.f;
        #pragma unroll
        for (int t = 0; t < 3; t++) {
            int k = lane + t * 32;
            if (k < NTOK) {
                float p = __expf(s[t] - mx);
                sum += p;
                Ps[warp * 96 + k] = p;
            }
        }
        sum = wred_sum(sum);
        float inv = 1.f / sum;
        __syncwarp();
        #pragma unroll
        for (int t = 0; t < 2; t++) {
            int d = lane + t * 32;
            float o = 0.f;
            for (int k = 0; k < NTOK; k++) o += Ps[warp * 96 + k] * Vs[k * KPAD + d];
            o *= inv;
            __nv_bfloat16 hh, ll;
            split_bf16(o, hh, ll);
            size_t oidx = ((size_t)b * NTOK + r) * DIM + h * HD + d;
            ohi[oidx] = hh;
            olo[oidx] = ll;
        }
        __syncwarp();
    }
}

// ---------------------------------------------------------------------------
extern "C" void kernel_launch(void* const* d_in, const int* in_sizes, int n_in,
                              void* d_out, int out_size) {
    const float* x      = (const float*)d_in[0];
    const float* coords = (const float*)d_in[1];
    const float* ln1_w  = (const float*)d_in[2];
    const float* ln1_b  = (const float*)d_in[3];
    const float* qkv_w  = (const float*)d_in[4];
    const float* qkv_b  = (const float*)d_in[5];
    const float* proj_w = (const float*)d_in[6];
    const float* proj_b = (const float*)d_in[7];
    const float* ln2_w  = (const float*)d_in[8];
    const float* ln2_b  = (const float*)d_in[9];
    const float* fc1_w  = (const float*)d_in[10];
    const float* fc1_b  = (const float*)d_in[11];
    const float* fc2_w  = (const float*)d_in[12];
    const float* fc2_b  = (const float*)d_in[13];
    const float* lnf_w  = (const float*)d_in[14];
    const float* lnf_b  = (const float*)d_in[15];
    float* out = (float*)d_out;

    float *gx, *gqkv;
    __nv_bfloat16 *a5h, *a5l, *a2h, *a2l, *whi, *wlo;
    cudaGetSymbolAddress((void**)&gx, g_x);
    cudaGetSymbolAddress((void**)&gqkv, g_qkv);
    cudaGetSymbolAddress((void**)&a5h, g_a512hi);
    cudaGetSymbolAddress((void**)&a5l, g_a512lo);
    cudaGetSymbolAddress((void**)&a2h, g_a2048hi);
    cudaGetSymbolAddress((void**)&a2l, g_a2048lo);
    cudaGetSymbolAddress((void**)&whi, g_whi);
    cudaGetSymbolAddress((void**)&wlo, g_wlo);

    static int attr_set = 0;
    if (!attr_set) {
        cudaFuncSetAttribute(attn_kernel, cudaFuncAttributeMaxDynamicSharedMemorySize, ATTN_SMEM);
        cudaFuncSetAttribute(mma_gemm<0>, cudaFuncAttributeMaxDynamicSharedMemorySize, GSMEMB);
        cudaFuncSetAttribute(mma_gemm<1>, cudaFuncAttributeMaxDynamicSharedMemorySize, GSMEMB);
        cudaFuncSetAttribute(mma_gemm<2>, cudaFuncAttributeMaxDynamicSharedMemorySize, GSMEMB);
        attr_set = 1;
    }

    // Weight prep: transpose + bf16 hi/lo split
    for (int l = 0; l < 6; l++) {
        prep_w<<<dim3(QKVN / 32, DIM / 32), dim3(32, 8)>>>(
            qkv_w + (size_t)l * DIM * QKVN, whi + (size_t)l * LOFF + OFF_QKV,
            wlo + (size_t)l * LOFF + OFF_QKV, DIM, QKVN);
        prep_w<<<dim3(DIM / 32, DIM / 32), dim3(32, 8)>>>(
            proj_w + (size_t)l * DIM * DIM, whi + (size_t)l * LOFF + OFF_PROJ,
            wlo + (size_t)l * LOFF + OFF_PROJ, DIM, DIM);
        prep_w<<<dim3(FFN / 32, DIM / 32), dim3(32, 8)>>>(
            fc1_w + (size_t)l * DIM * FFN, whi + (size_t)l * LOFF + OFF_FC1,
            wlo + (size_t)l * LOFF + OFF_FC1, DIM, FFN);
        prep_w<<<dim3(DIM / 32, FFN / 32), dim3(32, 8)>>>(
            fc2_w + (size_t)l * FFN * DIM, whi + (size_t)l * LOFF + OFF_FC2,
            wlo + (size_t)l * LOFF + OFF_FC2, FFN, DIM);
    }

    cudaMemcpyAsync(gx, x, (size_t)M_ROWS * DIM * sizeof(float), cudaMemcpyDeviceToDevice, 0);

    const int ln_grid = (M_ROWS + 7) / 8;
    const int rope_grid = (M_ROWS * HEADS * 16 + 255) / 256;

    for (int l = 0; l < 6; l++) {
        const __nv_bfloat16* qkvT_h = whi + (size_t)l * LOFF + OFF_QKV;
        const __nv_bfloat16* qkvT_l = wlo + (size_t)l * LOFF + OFF_QKV;
        const __nv_bfloat16* projT_h = whi + (size_t)l * LOFF + OFF_PROJ;
        const __nv_bfloat16* projT_l = wlo + (size_t)l * LOFF + OFF_PROJ;
        const __nv_bfloat16* fc1T_h = whi + (size_t)l * LOFF + OFF_FC1;
        const __nv_bfloat16* fc1T_l = wlo + (size_t)l * LOFF + OFF_FC1;
        const __nv_bfloat16* fc2T_h = whi + (size_t)l * LOFF + OFF_FC2;
        const __nv_bfloat16* fc2T_l = wlo + (size_t)l * LOFF + OFF_FC2;

        // LN1 -> bf16 hi/lo
        ln_kernel<1><<<ln_grid, 256>>>(gx, ln1_w + l * DIM, ln1_b + l * DIM, nullptr, a5h, a5l);
        // QKV GEMM -> fp32 qkv
        mma_gemm<0><<<dim3(QKVN / 128, M_ROWS / 128), 256, GSMEMB>>>(
            a5h, a5l, qkvT_h, qkvT_l, qkv_b + (size_t)l * QKVN, nullptr,
            gqkv, nullptr, nullptr, M_ROWS, QKVN, DIM);
        // RoPE
        rope_kernel<<<rope_grid, 256>>>(gqkv, coords);
        // Attention -> bf16 hi/lo
        attn_kernel<<<BATCH * HEADS, 256, ATTN_SMEM>>>(gqkv, a5h, a5l);
        // proj GEMM + residual -> g_x
        mma_gemm<2><<<dim3(DIM / 128, M_ROWS / 128), 256, GSMEMB>>>(
            a5h, a5l, projT_h, projT_l, proj_b + (size_t)l * DIM, gx,
            gx, nullptr, nullptr, M_ROWS, DIM, DIM);
        // LN2 -> bf16 hi/lo
        ln_kernel<1><<<ln_grid, 256>>>(gx, ln2_w + l * DIM, ln2_b + l * DIM, nullptr, a5h, a5l);
        // fc1 + GELU -> bf16 hi/lo
        mma_gemm<1><<<dim3(FFN / 128, M_ROWS / 128), 256, GSMEMB>>>(
            a5h, a5l, fc1T_h, fc1T_l, fc1_b + (size_t)l * FFN, nullptr,
            nullptr, a2h, a2l, M_ROWS, FFN, DIM);
        // fc2 + residual -> g_x
        mma_gemm<2><<<dim3(DIM / 128, M_ROWS / 128), 256, GSMEMB>>>(
            a2h, a2l, fc2T_h, fc2T_l, fc2_b + (size_t)l * DIM, gx,
            gx, nullptr, nullptr, M_ROWS, DIM, FFN);
    }
    // Final LN -> out (fp32)
    ln_kernel<0><<<ln_grid, 256>>>(gx, lnf_w, lnf_b, out, nullptr, nullptr);
}